// round 1
// baseline (speedup 1.0000x reference)
#include <cuda_runtime.h>
#include <math.h>

#define B_   32
#define S_   1024
#define DM   48
#define NH   3
#define DK   16
#define BH_  (B_*NH)            // 96
#define H_ELEMS (B_*S_*DM)      // 1572864

// Scratch (no allocations allowed in kernel_launch)
__device__ float g_Q[BH_*S_*DK];
__device__ float g_K[BH_*S_*DK];
__device__ float g_V[BH_*S_*DK];
__device__ float g_Hcat[B_*S_*DM];

// ---------------------------------------------------------------------------
// linear48: Y = X @ W^T + b  for X:[32768,48], W:[48,48], b:[48]
// mode 0: X := g_Hcat (internal), write out0[i*48+j]   (output projection)
// mode 1: write g_Q head-split, scale=0.25 folded
// mode 2: write g_K head-split
// mode 3: write g_V head-split
// ---------------------------------------------------------------------------
__global__ __launch_bounds__(384) void linear48(const float* __restrict__ X,
                                                const float* __restrict__ W,
                                                const float* __restrict__ bias,
                                                float* __restrict__ out0,
                                                int mode, float scale)
{
    __shared__ float Ws[48*49];
    __shared__ float bs[48];
    __shared__ float Xs[32][48];

    const float* Xp = (mode == 0) ? (const float*)g_Hcat : X;
    int tid = threadIdx.x;
    for (int i = tid; i < 48*48; i += 384) Ws[(i/48)*49 + (i%48)] = W[i];
    if (tid < 48) bs[tid] = bias[tid];
    int row0 = blockIdx.x * 32;
    for (int i = tid; i < 32*48; i += 384) Xs[i/48][i%48] = Xp[row0*48 + i];
    __syncthreads();

    int j  = tid % 48;
    int r0 = tid / 48;   // 0..7
#pragma unroll
    for (int rr = 0; rr < 4; rr++) {
        int r = r0 + rr*8;
        float acc = bs[j];
#pragma unroll
        for (int c = 0; c < 48; c++) acc = fmaf(Xs[r][c], Ws[j*49 + c], acc);
        acc *= scale;
        int grow = row0 + r;
        if (mode == 0) {
            out0[grow*48 + j] = acc;
        } else {
            int b = grow >> 10, s = grow & 1023;
            int h = j >> 4,    d = j & 15;
            float* dst = (mode == 1) ? g_Q : (mode == 2) ? g_K : g_V;
            dst[((b*NH + h)*S_ + s)*DK + d] = acc;
        }
    }
}

// ---------------------------------------------------------------------------
// Attention: per block = one (b*h) pair x one 256-row q chunk.
// K,V tiles in smem (rows padded to 20 floats -> conflict-free float4 LDS).
// Each warp: 32 q rows in groups of 4 (register blocked).
// Pass 1: s = q.k, e = expf(s) -> streamed to A (gmem), lsum += e, acc += e*V.
// Pass 2: rescale the warp-private A rows by 1/lsum (gmem re-read, L2-heavy).
// No max-subtraction: scores ~ N(0,1); exp cannot overflow fp32 here and the
// result is mathematically identical to softmax-with-max.
// ---------------------------------------------------------------------------
__global__ __launch_bounds__(256, 1) void attn_kernel(float* __restrict__ Aout)
{
    extern __shared__ float sm[];
    float4* Ks4 = (float4*)sm;                 // 1024 rows x 5 float4 (stride 20 floats)
    float4* Vs4 = (float4*)(sm + S_*20);

    int bh = blockIdx.x;      // 0..95
    int qc = blockIdx.y;      // 0..3
    const float4* Kg = (const float4*)(g_K + bh*S_*DK);
    const float4* Vg = (const float4*)(g_V + bh*S_*DK);
    for (int i = threadIdx.x; i < S_*4; i += 256) {
        int k = i >> 2, c = i & 3;
        Ks4[k*5 + c] = Kg[i];
        Vs4[k*5 + c] = Vg[i];
    }
    __syncthreads();

    int warp = threadIdx.x >> 5;
    int lane = threadIdx.x & 31;
    int b = bh / NH, h = bh % NH;

    for (int g = 0; g < 8; g++) {
        int q0 = qc*256 + warp*32 + g*4;

        float4 qv[4][4];
#pragma unroll
        for (int r = 0; r < 4; r++) {
            const float4* qp = (const float4*)(g_Q + (bh*S_ + q0 + r)*DK);
#pragma unroll
            for (int c = 0; c < 4; c++) qv[r][c] = qp[c];
        }

        float acc[4][16];
        float lsum[4];
#pragma unroll
        for (int r = 0; r < 4; r++) {
            lsum[r] = 0.f;
#pragma unroll
            for (int d = 0; d < 16; d++) acc[r][d] = 0.f;
        }

        for (int kc = 0; kc < S_; kc += 32) {
            int k = kc + lane;
            float4 k0 = Ks4[k*5+0], k1 = Ks4[k*5+1], k2 = Ks4[k*5+2], k3 = Ks4[k*5+3];
            float e[4];
#pragma unroll
            for (int r = 0; r < 4; r++) {
                float s;
                s = qv[r][0].x * k0.x;
                s = fmaf(qv[r][0].y, k0.y, s);
                s = fmaf(qv[r][0].z, k0.z, s);
                s = fmaf(qv[r][0].w, k0.w, s);
                s = fmaf(qv[r][1].x, k1.x, s);
                s = fmaf(qv[r][1].y, k1.y, s);
                s = fmaf(qv[r][1].z, k1.z, s);
                s = fmaf(qv[r][1].w, k1.w, s);
                s = fmaf(qv[r][2].x, k2.x, s);
                s = fmaf(qv[r][2].y, k2.y, s);
                s = fmaf(qv[r][2].z, k2.z, s);
                s = fmaf(qv[r][2].w, k2.w, s);
                s = fmaf(qv[r][3].x, k3.x, s);
                s = fmaf(qv[r][3].y, k3.y, s);
                s = fmaf(qv[r][3].z, k3.z, s);
                s = fmaf(qv[r][3].w, k3.w, s);
                float ev = __expf(s);
                e[r] = ev;
                lsum[r] += ev;
                Aout[(bh*S_ + q0 + r)*S_ + k] = ev;   // unnormalized, fixed in pass 2
            }
            float4 v0 = Vs4[k*5+0], v1 = Vs4[k*5+1], v2 = Vs4[k*5+2], v3 = Vs4[k*5+3];
#pragma unroll
            for (int r = 0; r < 4; r++) {
                float ev = e[r];
                acc[r][0]  = fmaf(ev, v0.x, acc[r][0]);
                acc[r][1]  = fmaf(ev, v0.y, acc[r][1]);
                acc[r][2]  = fmaf(ev, v0.z, acc[r][2]);
                acc[r][3]  = fmaf(ev, v0.w, acc[r][3]);
                acc[r][4]  = fmaf(ev, v1.x, acc[r][4]);
                acc[r][5]  = fmaf(ev, v1.y, acc[r][5]);
                acc[r][6]  = fmaf(ev, v1.z, acc[r][6]);
                acc[r][7]  = fmaf(ev, v1.w, acc[r][7]);
                acc[r][8]  = fmaf(ev, v2.x, acc[r][8]);
                acc[r][9]  = fmaf(ev, v2.y, acc[r][9]);
                acc[r][10] = fmaf(ev, v2.z, acc[r][10]);
                acc[r][11] = fmaf(ev, v2.w, acc[r][11]);
                acc[r][12] = fmaf(ev, v3.x, acc[r][12]);
                acc[r][13] = fmaf(ev, v3.y, acc[r][13]);
                acc[r][14] = fmaf(ev, v3.z, acc[r][14]);
                acc[r][15] = fmaf(ev, v3.w, acc[r][15]);
            }
        }

        // reduce row sums across warp
        float invl[4];
#pragma unroll
        for (int r = 0; r < 4; r++) {
            float v = lsum[r];
#pragma unroll
            for (int o = 16; o > 0; o >>= 1) v += __shfl_xor_sync(0xffffffffu, v, o);
            invl[r] = 1.0f / v;
        }
        // reduce AV partials across warp (all lanes end with totals)
#pragma unroll
        for (int r = 0; r < 4; r++)
#pragma unroll
            for (int d = 0; d < 16; d++) {
                float v = acc[r][d];
#pragma unroll
                for (int o = 16; o > 0; o >>= 1) v += __shfl_xor_sync(0xffffffffu, v, o);
                acc[r][d] = v;
            }

        if (lane == 0) {
#pragma unroll
            for (int r = 0; r < 4; r++) {
                float iv = invl[r];
                float4* hp = (float4*)(g_Hcat + (b*S_ + q0 + r)*DM + h*DK);
                hp[0] = make_float4(acc[r][0]*iv,  acc[r][1]*iv,  acc[r][2]*iv,  acc[r][3]*iv);
                hp[1] = make_float4(acc[r][4]*iv,  acc[r][5]*iv,  acc[r][6]*iv,  acc[r][7]*iv);
                hp[2] = make_float4(acc[r][8]*iv,  acc[r][9]*iv,  acc[r][10]*iv, acc[r][11]*iv);
                hp[3] = make_float4(acc[r][12]*iv, acc[r][13]*iv, acc[r][14]*iv, acc[r][15]*iv);
            }
        }

        // pass 2: normalize the 4 A rows this warp just wrote
        __threadfence_block();
        __syncwarp();
#pragma unroll
        for (int r = 0; r < 4; r++) {
            float iv = invl[r];
            float4* A4 = (float4*)(Aout + (bh*S_ + q0 + r)*S_);
            for (int i = lane; i < S_/4; i += 32) {
                float4 t = A4[i];
                t.x *= iv; t.y *= iv; t.z *= iv; t.w *= iv;
                A4[i] = t;
            }
        }
    }
}

// ---------------------------------------------------------------------------
extern "C" void kernel_launch(void* const* d_in, const int* in_sizes, int n_in,
                              void* d_out, int out_size)
{
    const float* Xq = (const float*)d_in[0];
    const float* Xk = (const float*)d_in[1];
    const float* Xv = (const float*)d_in[2];
    const float* Wq = (const float*)d_in[3];
    const float* bq = (const float*)d_in[4];
    const float* Wk = (const float*)d_in[5];
    const float* bk = (const float*)d_in[6];
    const float* Wv = (const float*)d_in[7];
    const float* bv = (const float*)d_in[8];
    const float* Wh = (const float*)d_in[9];
    const float* bh = (const float*)d_in[10];

    float* outH = (float*)d_out;
    float* outA = (float*)d_out + H_ELEMS;

    const int smem_bytes = S_*20*4*2;   // 160 KB
    cudaFuncSetAttribute(attn_kernel, cudaFuncAttributeMaxDynamicSharedMemorySize, smem_bytes);

    dim3 lgrid(B_*S_/32);   // 1024 blocks
    // Q = (Xq Wq^T + bq) * 1/sqrt(dk) ; K ; V   (head-split layouts)
    linear48<<<lgrid, 384>>>(Xq, Wq, bq, nullptr, 1, 0.25f);
    linear48<<<lgrid, 384>>>(Xk, Wk, bk, nullptr, 2, 1.0f);
    linear48<<<lgrid, 384>>>(Xv, Wv, bv, nullptr, 3, 1.0f);

    attn_kernel<<<dim3(BH_, 4), 256, smem_bytes>>>(outA);

    // H = Hcat Wh^T + bh
    linear48<<<lgrid, 384>>>(nullptr, Wh, bh, outH, 0, 1.0f);
}

// round 3
// speedup vs baseline: 1.0618x; 1.0618x over previous
#include <cuda_runtime.h>
#include <math.h>

#define B_   32
#define S_   1024
#define DM   48
#define NH   3
#define DK   16
#define BH_  (B_*NH)            // 96
#define H_ELEMS (B_*S_*DM)      // 1572864

typedef unsigned long long ull;

// Scratch (no allocations allowed)
__device__ float g_Q[BH_*S_*DK];
__device__ float g_K[BH_*S_*DK];
__device__ float g_V[BH_*S_*DK];
__device__ float g_Hcat[B_*S_*DM];

union F4U { float4 f4; ull u2[2]; float f[4]; };

// ---------------------------------------------------------------------------
// Linear core: Y = X @ W^T + b for a 128-row slab. 384 threads.
// thread -> (r0 = tid/12 in 0..31, jg = tid%12 -> cols jg*4..jg*4+3)
// rows r0 + 32*rr, rr<4.  16 outputs/thread, FMA:LDS = 2:1.
// ---------------------------------------------------------------------------
__device__ __forceinline__ void lin_core(const float* __restrict__ X,
    const float* __restrict__ W, const float* __restrict__ bias,
    int row0, float scale, float* __restrict__ out, int headsplit)
{
    __shared__ float Ws[48*49];
    __shared__ float bs[48];
    __shared__ float Xs[128*48];
    int tid = threadIdx.x;
    for (int i = tid; i < 48*48; i += 384) Ws[(i/48)*49 + (i%48)] = W[i];
    if (tid < 48) bs[tid] = bias[tid];
    const float4* Xg4 = (const float4*)(X + row0*48);
    float4* Xs4 = (float4*)Xs;
    for (int i = tid; i < 1536; i += 384) Xs4[i] = Xg4[i];
    __syncthreads();

    int r0 = tid / 12, jg = tid % 12;
    float acc[4][4];
#pragma unroll
    for (int rr = 0; rr < 4; rr++)
#pragma unroll
        for (int jj = 0; jj < 4; jj++) acc[rr][jj] = bs[jg*4 + jj];

#pragma unroll 4
    for (int c = 0; c < 48; c++) {
        float xv[4], wv[4];
#pragma unroll
        for (int rr = 0; rr < 4; rr++) xv[rr] = Xs[(r0 + 32*rr)*48 + c];
#pragma unroll
        for (int jj = 0; jj < 4; jj++) wv[jj] = Ws[(jg*4 + jj)*49 + c];
#pragma unroll
        for (int rr = 0; rr < 4; rr++)
#pragma unroll
            for (int jj = 0; jj < 4; jj++)
                acc[rr][jj] = fmaf(xv[rr], wv[jj], acc[rr][jj]);
    }

    int j0 = jg * 4;
#pragma unroll
    for (int rr = 0; rr < 4; rr++) {
        int grow = row0 + r0 + 32*rr;
        float4 v = make_float4(acc[rr][0]*scale, acc[rr][1]*scale,
                               acc[rr][2]*scale, acc[rr][3]*scale);
        if (headsplit) {
            int b = grow >> 10, s = grow & 1023;
            int h = j0 >> 4,  d = j0 & 15;
            *(float4*)(out + ((b*NH + h)*S_ + s)*DK + d) = v;
        } else {
            *(float4*)(out + grow*48 + j0) = v;
        }
    }
}

__global__ __launch_bounds__(384) void qkv48(
    const float* __restrict__ Xq, const float* __restrict__ Wq, const float* __restrict__ bq,
    const float* __restrict__ Xk, const float* __restrict__ Wk, const float* __restrict__ bk,
    const float* __restrict__ Xv, const float* __restrict__ Wv, const float* __restrict__ bv)
{
    int m = blockIdx.y;
    const float *X, *W, *bb; float* dst; float scale;
    if (m == 0)      { X = Xq; W = Wq; bb = bq; dst = g_Q; scale = 0.25f; }
    else if (m == 1) { X = Xk; W = Wk; bb = bk; dst = g_K; scale = 1.0f; }
    else             { X = Xv; W = Wv; bb = bv; dst = g_V; scale = 1.0f; }
    lin_core(X, W, bb, blockIdx.x * 128, scale, dst, 1);
}

__global__ __launch_bounds__(384) void proj48(
    const float* __restrict__ Wh, const float* __restrict__ bhp, float* __restrict__ out)
{
    lin_core((const float*)g_Hcat, Wh, bhp, blockIdx.x * 128, 1.0f, out, 0);
}

// ---------------------------------------------------------------------------
// Attention: block = (bh, 256 q-rows). 512 threads = 16 warps.
// Warp pair (g, half): both own the same 32 q rows (lane = row), each covers
// half the k range. K/V in smem, all K/V reads are warp-uniform (broadcast).
// Pass 1: lsum = sum exp(q.k) over the warp's k-half (f32x2 dot).
// Combine halves via smem -> inv.
// Pass 2: recompute e, scale by inv, stage into 32x33 transpose tile,
// coalesced A writes; AV accumulated lane-private in f32x2 regs.
// AV halves combined via smem; Hcat written.
// ---------------------------------------------------------------------------
#define SM_FLOATS 55296   // 32768 K/V + 16896 ebuf + 5120 avst + 512 lsm

__global__ __launch_bounds__(512, 1) void attn_kernel(float* __restrict__ Aout)
{
    extern __shared__ float sm[];
    float4* Ks4 = (float4*)sm;              // 1024 x 4 float4
    float4* Vs4 = (float4*)(sm + 16384);
    float*  ebuf = sm + 32768;              // 16 warps x 32 x 33
    float*  avst = sm + 49664;              // 8 groups x 32 x 20
    float*  lsm  = sm + 54784;              // 16 x 32

    int bh = blockIdx.x, qc = blockIdx.y;
    int tid = threadIdx.x, warp = tid >> 5, lane = tid & 31;
    int g = warp >> 1, half = warp & 1;
    int q0 = qc*256 + g*32;
    int row = q0 + lane;

    const float4* Kg = (const float4*)(g_K + bh*(S_*DK));
    const float4* Vg = (const float4*)(g_V + bh*(S_*DK));
    for (int i = tid; i < S_*4; i += 512) { Ks4[i] = Kg[i]; Vs4[i] = Vg[i]; }
    __syncthreads();

    F4U qu[4];
    const float4* qg = (const float4*)(g_Q + (bh*S_ + row)*DK);
#pragma unroll
    for (int i = 0; i < 4; i++) qu[i].f4 = qg[i];

    int kbase = half * 512;

    // ---- pass 1: row sums ----
    float lsum = 0.f;
#pragma unroll 4
    for (int kk = 0; kk < 512; kk++) {
        int k = kbase + kk;
        F4U k0, k1, k2, k3;
        k0.f4 = Ks4[k*4+0]; k1.f4 = Ks4[k*4+1]; k2.f4 = Ks4[k*4+2]; k3.f4 = Ks4[k*4+3];
        ull a;
        asm("mul.rn.f32x2 %0,%1,%2;"     : "=l"(a) : "l"(qu[0].u2[0]), "l"(k0.u2[0]));
        asm("fma.rn.f32x2 %0,%1,%2,%0;"  : "+l"(a) : "l"(qu[0].u2[1]), "l"(k0.u2[1]));
        asm("fma.rn.f32x2 %0,%1,%2,%0;"  : "+l"(a) : "l"(qu[1].u2[0]), "l"(k1.u2[0]));
        asm("fma.rn.f32x2 %0,%1,%2,%0;"  : "+l"(a) : "l"(qu[1].u2[1]), "l"(k1.u2[1]));
        asm("fma.rn.f32x2 %0,%1,%2,%0;"  : "+l"(a) : "l"(qu[2].u2[0]), "l"(k2.u2[0]));
        asm("fma.rn.f32x2 %0,%1,%2,%0;"  : "+l"(a) : "l"(qu[2].u2[1]), "l"(k2.u2[1]));
        asm("fma.rn.f32x2 %0,%1,%2,%0;"  : "+l"(a) : "l"(qu[3].u2[0]), "l"(k3.u2[0]));
        asm("fma.rn.f32x2 %0,%1,%2,%0;"  : "+l"(a) : "l"(qu[3].u2[1]), "l"(k3.u2[1]));
        float lo, hi;
        asm("mov.b64 {%0,%1},%2;" : "=f"(lo), "=f"(hi) : "l"(a));
        lsum += __expf(lo + hi);
    }
    lsm[warp*32 + lane] = lsum;
    __syncthreads();
    float inv = 1.0f / (lsum + lsm[(warp ^ 1)*32 + lane]);

    // ---- pass 2: write normalized A, accumulate AV ----
    ull acc[8];
#pragma unroll
    for (int j = 0; j < 8; j++) acc[j] = 0ULL;

    float* eb = ebuf + warp*1056;

    for (int kt = 0; kt < 512; kt += 32) {
#pragma unroll 2
        for (int kk = 0; kk < 32; kk++) {
            int k = kbase + kt + kk;
            F4U k0, k1, k2, k3;
            k0.f4 = Ks4[k*4+0]; k1.f4 = Ks4[k*4+1]; k2.f4 = Ks4[k*4+2]; k3.f4 = Ks4[k*4+3];
            ull a;
            asm("mul.rn.f32x2 %0,%1,%2;"     : "=l"(a) : "l"(qu[0].u2[0]), "l"(k0.u2[0]));
            asm("fma.rn.f32x2 %0,%1,%2,%0;"  : "+l"(a) : "l"(qu[0].u2[1]), "l"(k0.u2[1]));
            asm("fma.rn.f32x2 %0,%1,%2,%0;"  : "+l"(a) : "l"(qu[1].u2[0]), "l"(k1.u2[0]));
            asm("fma.rn.f32x2 %0,%1,%2,%0;"  : "+l"(a) : "l"(qu[1].u2[1]), "l"(k1.u2[1]));
            asm("fma.rn.f32x2 %0,%1,%2,%0;"  : "+l"(a) : "l"(qu[2].u2[0]), "l"(k2.u2[0]));
            asm("fma.rn.f32x2 %0,%1,%2,%0;"  : "+l"(a) : "l"(qu[2].u2[1]), "l"(k2.u2[1]));
            asm("fma.rn.f32x2 %0,%1,%2,%0;"  : "+l"(a) : "l"(qu[3].u2[0]), "l"(k3.u2[0]));
            asm("fma.rn.f32x2 %0,%1,%2,%0;"  : "+l"(a) : "l"(qu[3].u2[1]), "l"(k3.u2[1]));
            float lo, hi;
            asm("mov.b64 {%0,%1},%2;" : "=f"(lo), "=f"(hi) : "l"(a));
            float es = __expf(lo + hi) * inv;
            eb[lane*33 + kk] = es;

            ull ee; asm("mov.b64 %0,{%1,%1};" : "=l"(ee) : "f"(es));
            F4U v0, v1, v2, v3;
            v0.f4 = Vs4[k*4+0]; v1.f4 = Vs4[k*4+1]; v2.f4 = Vs4[k*4+2]; v3.f4 = Vs4[k*4+3];
            asm("fma.rn.f32x2 %0,%1,%2,%0;" : "+l"(acc[0]) : "l"(ee), "l"(v0.u2[0]));
            asm("fma.rn.f32x2 %0,%1,%2,%0;" : "+l"(acc[1]) : "l"(ee), "l"(v0.u2[1]));
            asm("fma.rn.f32x2 %0,%1,%2,%0;" : "+l"(acc[2]) : "l"(ee), "l"(v1.u2[0]));
            asm("fma.rn.f32x2 %0,%1,%2,%0;" : "+l"(acc[3]) : "l"(ee), "l"(v1.u2[1]));
            asm("fma.rn.f32x2 %0,%1,%2,%0;" : "+l"(acc[4]) : "l"(ee), "l"(v2.u2[0]));
            asm("fma.rn.f32x2 %0,%1,%2,%0;" : "+l"(acc[5]) : "l"(ee), "l"(v2.u2[1]));
            asm("fma.rn.f32x2 %0,%1,%2,%0;" : "+l"(acc[6]) : "l"(ee), "l"(v3.u2[0]));
            asm("fma.rn.f32x2 %0,%1,%2,%0;" : "+l"(acc[7]) : "l"(ee), "l"(v3.u2[1]));
        }
        __syncwarp();
        // coalesced A drain: 32 rows x 128B
#pragma unroll 4
        for (int r = 0; r < 32; r++) {
            float val = eb[r*33 + lane];
            Aout[(bh*S_ + q0 + r)*S_ + kbase + kt + lane] = val;
        }
        __syncwarp();
    }

    // ---- AV combine across the warp pair ----
    float facc[16];
#pragma unroll
    for (int j = 0; j < 8; j++)
        asm("mov.b64 {%0,%1},%2;" : "=f"(facc[2*j]), "=f"(facc[2*j+1]) : "l"(acc[j]));

    if (half == 1) {
        float4* st = (float4*)(avst + (g*32 + lane)*20);
        st[0] = make_float4(facc[0],  facc[1],  facc[2],  facc[3]);
        st[1] = make_float4(facc[4],  facc[5],  facc[6],  facc[7]);
        st[2] = make_float4(facc[8],  facc[9],  facc[10], facc[11]);
        st[3] = make_float4(facc[12], facc[13], facc[14], facc[15]);
    }
    __syncthreads();
    if (half == 0) {
        const float4* st = (const float4*)(avst + (g*32 + lane)*20);
        int b = bh / NH, h = bh % NH;
        float4* hp = (float4*)(g_Hcat + (b*S_ + row)*DM + h*DK);
        float4 t;
        t = st[0]; hp[0] = make_float4(facc[0]+t.x,  facc[1]+t.y,  facc[2]+t.z,  facc[3]+t.w);
        t = st[1]; hp[1] = make_float4(facc[4]+t.x,  facc[5]+t.y,  facc[6]+t.z,  facc[7]+t.w);
        t = st[2]; hp[2] = make_float4(facc[8]+t.x,  facc[9]+t.y,  facc[10]+t.z, facc[11]+t.w);
        t = st[3]; hp[3] = make_float4(facc[12]+t.x, facc[13]+t.y, facc[14]+t.z, facc[15]+t.w);
    }
}

// ---------------------------------------------------------------------------
extern "C" void kernel_launch(void* const* d_in, const int* in_sizes, int n_in,
                              void* d_out, int out_size)
{
    const float* Xq = (const float*)d_in[0];
    const float* Xk = (const float*)d_in[1];
    const float* Xv = (const float*)d_in[2];
    const float* Wq = (const float*)d_in[3];
    const float* bq = (const float*)d_in[4];
    const float* Wk = (const float*)d_in[5];
    const float* bk = (const float*)d_in[6];
    const float* Wv = (const float*)d_in[7];
    const float* bv = (const float*)d_in[8];
    const float* Wh = (const float*)d_in[9];
    const float* bh = (const float*)d_in[10];

    float* outH = (float*)d_out;
    float* outA = (float*)d_out + H_ELEMS;

    const int smem_bytes = SM_FLOATS * 4;   // 221184 B
    cudaFuncSetAttribute(attn_kernel, cudaFuncAttributeMaxDynamicSharedMemorySize, smem_bytes);

    qkv48<<<dim3(256, 3), 384>>>(Xq, Wq, bq, Xk, Wk, bk, Xv, Wv, bv);
    attn_kernel<<<dim3(BH_, 4), 512, smem_bytes>>>(outA);
    proj48<<<256, 384>>>(Wh, bh, outH);
}

// round 4
// speedup vs baseline: 1.0622x; 1.0003x over previous
#include <cuda_runtime.h>
#include <math.h>

#define B_   32
#define S_   1024
#define DM   48
#define NH   3
#define DK   16
#define BH_  (B_*NH)            // 96
#define H_ELEMS (B_*S_*DM)      // 1572864

typedef unsigned long long ull;

// Scratch (no allocations allowed)
__device__ float g_Q[BH_*S_*DK];
__device__ float g_K[BH_*S_*DK];
__device__ float g_V[BH_*S_*DK];
__device__ float g_Hcat[B_*S_*DM];

union F4U { float4 f4; ull u2[2]; float f[4]; };

// ---------------------------------------------------------------------------
// Linear core: Y = X @ W^T + b for a 128-row slab. 384 threads.
// thread -> (r0 = tid/12 in 0..31, jg = tid%12 -> cols jg*4..jg*4+3)
// rows r0 + 32*rr, rr<4.  16 outputs/thread, FMA:LDS = 2:1.
// ---------------------------------------------------------------------------
__device__ __forceinline__ void lin_core(const float* __restrict__ X,
    const float* __restrict__ W, const float* __restrict__ bias,
    int row0, float scale, float* __restrict__ out, int headsplit)
{
    __shared__ float Ws[48*49];
    __shared__ float bs[48];
    __shared__ float Xs[128*48];
    int tid = threadIdx.x;
    for (int i = tid; i < 48*48; i += 384) Ws[(i/48)*49 + (i%48)] = W[i];
    if (tid < 48) bs[tid] = bias[tid];
    const float4* Xg4 = (const float4*)(X + row0*48);
    float4* Xs4 = (float4*)Xs;
    for (int i = tid; i < 1536; i += 384) Xs4[i] = Xg4[i];
    __syncthreads();

    int r0 = tid / 12, jg = tid % 12;
    float acc[4][4];
#pragma unroll
    for (int rr = 0; rr < 4; rr++)
#pragma unroll
        for (int jj = 0; jj < 4; jj++) acc[rr][jj] = bs[jg*4 + jj];

#pragma unroll 4
    for (int c = 0; c < 48; c++) {
        float xv[4], wv[4];
#pragma unroll
        for (int rr = 0; rr < 4; rr++) xv[rr] = Xs[(r0 + 32*rr)*48 + c];
#pragma unroll
        for (int jj = 0; jj < 4; jj++) wv[jj] = Ws[(jg*4 + jj)*49 + c];
#pragma unroll
        for (int rr = 0; rr < 4; rr++)
#pragma unroll
            for (int jj = 0; jj < 4; jj++)
                acc[rr][jj] = fmaf(xv[rr], wv[jj], acc[rr][jj]);
    }

    int j0 = jg * 4;
#pragma unroll
    for (int rr = 0; rr < 4; rr++) {
        int grow = row0 + r0 + 32*rr;
        float4 v = make_float4(acc[rr][0]*scale, acc[rr][1]*scale,
                               acc[rr][2]*scale, acc[rr][3]*scale);
        if (headsplit) {
            int b = grow >> 10, s = grow & 1023;
            int h = j0 >> 4,  d = j0 & 15;
            *(float4*)(out + ((b*NH + h)*S_ + s)*DK + d) = v;
        } else {
            *(float4*)(out + grow*48 + j0) = v;
        }
    }
}

__global__ __launch_bounds__(384) void qkv48(
    const float* __restrict__ Xq, const float* __restrict__ Wq, const float* __restrict__ bq,
    const float* __restrict__ Xk, const float* __restrict__ Wk, const float* __restrict__ bk,
    const float* __restrict__ Xv, const float* __restrict__ Wv, const float* __restrict__ bv)
{
    int m = blockIdx.y;
    const float *X, *W, *bb; float* dst; float scale;
    if (m == 0)      { X = Xq; W = Wq; bb = bq; dst = g_Q; scale = 0.25f; }
    else if (m == 1) { X = Xk; W = Wk; bb = bk; dst = g_K; scale = 1.0f; }
    else             { X = Xv; W = Wv; bb = bv; dst = g_V; scale = 1.0f; }
    lin_core(X, W, bb, blockIdx.x * 128, scale, dst, 1);
}

__global__ __launch_bounds__(384) void proj48(
    const float* __restrict__ Wh, const float* __restrict__ bhp, float* __restrict__ out)
{
    lin_core((const float*)g_Hcat, Wh, bhp, blockIdx.x * 128, 1.0f, out, 0);
}

// ---------------------------------------------------------------------------
// Attention: block = (bh, 256 q-rows). 512 threads = 16 warps.
// Warp pair (g, half): both own the same 32 q rows (lane = row), each covers
// half the k range. K/V in smem, all K/V reads are warp-uniform (broadcast).
// Pass 1: lsum = sum exp(q.k) over the warp's k-half (f32x2 dot).
// Combine halves via smem -> inv.
// Pass 2: recompute e, scale by inv, stage into 32x33 transpose tile,
// coalesced A writes; AV accumulated lane-private in f32x2 regs.
// AV halves combined via smem; Hcat written.
// ---------------------------------------------------------------------------
#define SM_FLOATS 55296   // 32768 K/V + 16896 ebuf + 5120 avst + 512 lsm

__global__ __launch_bounds__(512, 1) void attn_kernel(float* __restrict__ Aout)
{
    extern __shared__ float sm[];
    float4* Ks4 = (float4*)sm;              // 1024 x 4 float4
    float4* Vs4 = (float4*)(sm + 16384);
    float*  ebuf = sm + 32768;              // 16 warps x 32 x 33
    float*  avst = sm + 49664;              // 8 groups x 32 x 20
    float*  lsm  = sm + 54784;              // 16 x 32

    int bh = blockIdx.x, qc = blockIdx.y;
    int tid = threadIdx.x, warp = tid >> 5, lane = tid & 31;
    int g = warp >> 1, half = warp & 1;
    int q0 = qc*256 + g*32;
    int row = q0 + lane;

    const float4* Kg = (const float4*)(g_K + bh*(S_*DK));
    const float4* Vg = (const float4*)(g_V + bh*(S_*DK));
    for (int i = tid; i < S_*4; i += 512) { Ks4[i] = Kg[i]; Vs4[i] = Vg[i]; }
    __syncthreads();

    F4U qu[4];
    const float4* qg = (const float4*)(g_Q + (bh*S_ + row)*DK);
#pragma unroll
    for (int i = 0; i < 4; i++) qu[i].f4 = qg[i];

    int kbase = half * 512;

    // ---- pass 1: row sums ----
    float lsum = 0.f;
#pragma unroll 4
    for (int kk = 0; kk < 512; kk++) {
        int k = kbase + kk;
        F4U k0, k1, k2, k3;
        k0.f4 = Ks4[k*4+0]; k1.f4 = Ks4[k*4+1]; k2.f4 = Ks4[k*4+2]; k3.f4 = Ks4[k*4+3];
        ull a;
        asm("mul.rn.f32x2 %0,%1,%2;"     : "=l"(a) : "l"(qu[0].u2[0]), "l"(k0.u2[0]));
        asm("fma.rn.f32x2 %0,%1,%2,%0;"  : "+l"(a) : "l"(qu[0].u2[1]), "l"(k0.u2[1]));
        asm("fma.rn.f32x2 %0,%1,%2,%0;"  : "+l"(a) : "l"(qu[1].u2[0]), "l"(k1.u2[0]));
        asm("fma.rn.f32x2 %0,%1,%2,%0;"  : "+l"(a) : "l"(qu[1].u2[1]), "l"(k1.u2[1]));
        asm("fma.rn.f32x2 %0,%1,%2,%0;"  : "+l"(a) : "l"(qu[2].u2[0]), "l"(k2.u2[0]));
        asm("fma.rn.f32x2 %0,%1,%2,%0;"  : "+l"(a) : "l"(qu[2].u2[1]), "l"(k2.u2[1]));
        asm("fma.rn.f32x2 %0,%1,%2,%0;"  : "+l"(a) : "l"(qu[3].u2[0]), "l"(k3.u2[0]));
        asm("fma.rn.f32x2 %0,%1,%2,%0;"  : "+l"(a) : "l"(qu[3].u2[1]), "l"(k3.u2[1]));
        float lo, hi;
        asm("mov.b64 {%0,%1},%2;" : "=f"(lo), "=f"(hi) : "l"(a));
        lsum += __expf(lo + hi);
    }
    lsm[warp*32 + lane] = lsum;
    __syncthreads();
    float inv = 1.0f / (lsum + lsm[(warp ^ 1)*32 + lane]);

    // ---- pass 2: write normalized A, accumulate AV ----
    ull acc[8];
#pragma unroll
    for (int j = 0; j < 8; j++) acc[j] = 0ULL;

    float* eb = ebuf + warp*1056;

    for (int kt = 0; kt < 512; kt += 32) {
#pragma unroll 2
        for (int kk = 0; kk < 32; kk++) {
            int k = kbase + kt + kk;
            F4U k0, k1, k2, k3;
            k0.f4 = Ks4[k*4+0]; k1.f4 = Ks4[k*4+1]; k2.f4 = Ks4[k*4+2]; k3.f4 = Ks4[k*4+3];
            ull a;
            asm("mul.rn.f32x2 %0,%1,%2;"     : "=l"(a) : "l"(qu[0].u2[0]), "l"(k0.u2[0]));
            asm("fma.rn.f32x2 %0,%1,%2,%0;"  : "+l"(a) : "l"(qu[0].u2[1]), "l"(k0.u2[1]));
            asm("fma.rn.f32x2 %0,%1,%2,%0;"  : "+l"(a) : "l"(qu[1].u2[0]), "l"(k1.u2[0]));
            asm("fma.rn.f32x2 %0,%1,%2,%0;"  : "+l"(a) : "l"(qu[1].u2[1]), "l"(k1.u2[1]));
            asm("fma.rn.f32x2 %0,%1,%2,%0;"  : "+l"(a) : "l"(qu[2].u2[0]), "l"(k2.u2[0]));
            asm("fma.rn.f32x2 %0,%1,%2,%0;"  : "+l"(a) : "l"(qu[2].u2[1]), "l"(k2.u2[1]));
            asm("fma.rn.f32x2 %0,%1,%2,%0;"  : "+l"(a) : "l"(qu[3].u2[0]), "l"(k3.u2[0]));
            asm("fma.rn.f32x2 %0,%1,%2,%0;"  : "+l"(a) : "l"(qu[3].u2[1]), "l"(k3.u2[1]));
            float lo, hi;
            asm("mov.b64 {%0,%1},%2;" : "=f"(lo), "=f"(hi) : "l"(a));
            float es = __expf(lo + hi) * inv;
            eb[lane*33 + kk] = es;

            ull ee; asm("mov.b64 %0,{%1,%1};" : "=l"(ee) : "f"(es));
            F4U v0, v1, v2, v3;
            v0.f4 = Vs4[k*4+0]; v1.f4 = Vs4[k*4+1]; v2.f4 = Vs4[k*4+2]; v3.f4 = Vs4[k*4+3];
            asm("fma.rn.f32x2 %0,%1,%2,%0;" : "+l"(acc[0]) : "l"(ee), "l"(v0.u2[0]));
            asm("fma.rn.f32x2 %0,%1,%2,%0;" : "+l"(acc[1]) : "l"(ee), "l"(v0.u2[1]));
            asm("fma.rn.f32x2 %0,%1,%2,%0;" : "+l"(acc[2]) : "l"(ee), "l"(v1.u2[0]));
            asm("fma.rn.f32x2 %0,%1,%2,%0;" : "+l"(acc[3]) : "l"(ee), "l"(v1.u2[1]));
            asm("fma.rn.f32x2 %0,%1,%2,%0;" : "+l"(acc[4]) : "l"(ee), "l"(v2.u2[0]));
            asm("fma.rn.f32x2 %0,%1,%2,%0;" : "+l"(acc[5]) : "l"(ee), "l"(v2.u2[1]));
            asm("fma.rn.f32x2 %0,%1,%2,%0;" : "+l"(acc[6]) : "l"(ee), "l"(v3.u2[0]));
            asm("fma.rn.f32x2 %0,%1,%2,%0;" : "+l"(acc[7]) : "l"(ee), "l"(v3.u2[1]));
        }
        __syncwarp();
        // coalesced A drain: 32 rows x 128B
#pragma unroll 4
        for (int r = 0; r < 32; r++) {
            float val = eb[r*33 + lane];
            Aout[(bh*S_ + q0 + r)*S_ + kbase + kt + lane] = val;
        }
        __syncwarp();
    }

    // ---- AV combine across the warp pair ----
    float facc[16];
#pragma unroll
    for (int j = 0; j < 8; j++)
        asm("mov.b64 {%0,%1},%2;" : "=f"(facc[2*j]), "=f"(facc[2*j+1]) : "l"(acc[j]));

    if (half == 1) {
        float4* st = (float4*)(avst + (g*32 + lane)*20);
        st[0] = make_float4(facc[0],  facc[1],  facc[2],  facc[3]);
        st[1] = make_float4(facc[4],  facc[5],  facc[6],  facc[7]);
        st[2] = make_float4(facc[8],  facc[9],  facc[10], facc[11]);
        st[3] = make_float4(facc[12], facc[13], facc[14], facc[15]);
    }
    __syncthreads();
    if (half == 0) {
        const float4* st = (const float4*)(avst + (g*32 + lane)*20);
        int b = bh / NH, h = bh % NH;
        float4* hp = (float4*)(g_Hcat + (b*S_ + row)*DM + h*DK);
        float4 t;
        t = st[0]; hp[0] = make_float4(facc[0]+t.x,  facc[1]+t.y,  facc[2]+t.z,  facc[3]+t.w);
        t = st[1]; hp[1] = make_float4(facc[4]+t.x,  facc[5]+t.y,  facc[6]+t.z,  facc[7]+t.w);
        t = st[2]; hp[2] = make_float4(facc[8]+t.x,  facc[9]+t.y,  facc[10]+t.z, facc[11]+t.w);
        t = st[3]; hp[3] = make_float4(facc[12]+t.x, facc[13]+t.y, facc[14]+t.z, facc[15]+t.w);
    }
}

// ---------------------------------------------------------------------------
extern "C" void kernel_launch(void* const* d_in, const int* in_sizes, int n_in,
                              void* d_out, int out_size)
{
    const float* Xq = (const float*)d_in[0];
    const float* Xk = (const float*)d_in[1];
    const float* Xv = (const float*)d_in[2];
    const float* Wq = (const float*)d_in[3];
    const float* bq = (const float*)d_in[4];
    const float* Wk = (const float*)d_in[5];
    const float* bk = (const float*)d_in[6];
    const float* Wv = (const float*)d_in[7];
    const float* bv = (const float*)d_in[8];
    const float* Wh = (const float*)d_in[9];
    const float* bh = (const float*)d_in[10];

    float* outH = (float*)d_out;
    float* outA = (float*)d_out + H_ELEMS;

    const int smem_bytes = SM_FLOATS * 4;   // 221184 B
    cudaFuncSetAttribute(attn_kernel, cudaFuncAttributeMaxDynamicSharedMemorySize, smem_bytes);

    qkv48<<<dim3(256, 3), 384>>>(Xq, Wq, bq, Xk, Wk, bk, Xv, Wv, bv);
    attn_kernel<<<dim3(BH_, 4), 512, smem_bytes>>>(outA);
    proj48<<<256, 384>>>(Wh, bh, outH);
}